// round 5
// baseline (speedup 1.0000x reference)
#include <cuda_runtime.h>

// Fixed shapes per reference: B=4096, IN=HID=8192, fp32
#define IN_DIM    8192
#define HID_DIM   8192
#define COL4      (IN_DIM / 4)        // 2048 float4 per W/x row
#define NCHUNK    8
#define CHUNK_F4  (COL4 / NCHUNK)     // 256 float4 = 1024 floats per chunk

// Device-global scratch (allocation-free rule: device globals allowed)
__device__ float g_wsum[IN_DIM];      // 32 KB
__device__ float g_acc[4096];         // per-row accumulator across chunks

// ---- colsum_chunk: wsum for column-chunk c = sum over 8192 rows of W ----
// grid = 32 blocks, block = 256. Block b owns 8 float4 columns
// (cols c*256 + b*8 .. +7). Thread t: col = t&7, row-group = t>>3 (32 groups
// of 256 rows). Warp = 8 cols x 4 groups -> 4 full 128B lines per load step.
__global__ __launch_bounds__(256) void colsum_chunk(const float* __restrict__ w,
                                                    int c) {
    const int t     = threadIdx.x;
    const int col   = t & 7;
    const int grp   = t >> 3;
    const int colf4 = c * CHUNK_F4 + blockIdx.x * 8 + col;
    const int r0    = grp * 256;
    const float4* __restrict__ w4 = reinterpret_cast<const float4*>(w);

    float4 acc = make_float4(0.f, 0.f, 0.f, 0.f);
    #pragma unroll 16
    for (int i = 0; i < 256; ++i) {
        float4 v = __ldg(&w4[(size_t)(r0 + i) * COL4 + colf4]);
        acc.x += v.x; acc.y += v.y; acc.z += v.z; acc.w += v.w;
    }

    __shared__ float4 s[256];
    s[t] = acc;
    __syncthreads();

    // lanes 0..7 of warp 0: reduce 32 groups for column `t` (fixed order)
    if (t < 8) {
        float4 sum = make_float4(0.f, 0.f, 0.f, 0.f);
        #pragma unroll
        for (int g = 0; g < 32; ++g) {
            float4 v = s[g * 8 + t];
            sum.x += v.x; sum.y += v.y; sum.z += v.z; sum.w += v.w;
        }
        reinterpret_cast<float4*>(g_wsum)[c * CHUNK_F4 + blockIdx.x * 8 + t] = sum;
    }
}

// ---- rowdot_chunk: g_acc[b] += dot(x[b, chunk c], wsum[chunk c]) ----
// grid = 512 blocks, block = 256. Block owns 8 rows; thread t owns float4
// column t of the chunk, 8 independent x loads (MLP=8), 1 L2-resident wsum
// load reused across the 8 rows. Last chunk scales by 0.75 and writes out.
__global__ __launch_bounds__(256) void rowdot_chunk(const float* __restrict__ x,
                                                    float* __restrict__ out,
                                                    int c, int is_last) {
    const int t     = threadIdx.x;
    const int lane  = t & 31;
    const int wid   = t >> 5;
    const int rbase = blockIdx.x * 8;
    const int i     = c * CHUNK_F4 + t;

    const float4* __restrict__ x4 = reinterpret_cast<const float4*>(x);
    const float4  wv = __ldg(&reinterpret_cast<const float4*>(g_wsum)[i]);

    float4 xv[8];
    #pragma unroll
    for (int r = 0; r < 8; ++r)
        xv[r] = __ldg(&x4[(size_t)(rbase + r) * COL4 + i]);

    float acc[8];
    #pragma unroll
    for (int r = 0; r < 8; ++r) {
        float a;
        a = xv[r].x * wv.x;
        a = fmaf(xv[r].y, wv.y, a);
        a = fmaf(xv[r].z, wv.z, a);
        a = fmaf(xv[r].w, wv.w, a);
        acc[r] = a;
    }

    #pragma unroll
    for (int r = 0; r < 8; ++r) {
        #pragma unroll
        for (int off = 16; off > 0; off >>= 1)
            acc[r] += __shfl_xor_sync(0xFFFFFFFFu, acc[r], off);
    }

    __shared__ float s[8][9];           // [row][warp], padded
    if (lane == 0) {
        #pragma unroll
        for (int r = 0; r < 8; ++r) s[r][wid] = acc[r];
    }
    __syncthreads();

    // warp r finalizes row r
    float v = (lane < 8) ? s[wid][lane] : 0.f;
    #pragma unroll
    for (int off = 4; off > 0; off >>= 1)
        v += __shfl_xor_sync(0xFFFFFFFFu, v, off);

    if (lane == 0) {
        const int row = rbase + wid;
        float total = (c == 0) ? v : (g_acc[row] + v);   // c==0 overwrites stale
        if (is_last) out[row] = total * 0.75f;           // (/2) * 1.5
        else         g_acc[row] = total;
    }
}

extern "C" void kernel_launch(void* const* d_in, const int* in_sizes, int n_in,
                              void* d_out, int out_size) {
    const float* x = (const float*)d_in[0];   // [B, IN]
    const float* w = (const float*)d_in[1];   // [HID, IN]
    float* out = (float*)d_out;               // [B, 1]

    // One-time infrastructure (host objects only; no device memory)
    static cudaStream_t sA = nullptr;
    static cudaEvent_t  evFork = nullptr;
    static cudaEvent_t  ev[NCHUNK];
    if (!sA) {
        cudaStreamCreateWithFlags(&sA, cudaStreamNonBlocking);
        cudaEventCreateWithFlags(&evFork, cudaEventDisableTiming);
        for (int c = 0; c < NCHUNK; ++c)
            cudaEventCreateWithFlags(&ev[c], cudaEventDisableTiming);
    }

    // Fork: sA becomes capture-dependent on the main stream
    cudaEventRecord(evFork, 0);
    cudaStreamWaitEvent(sA, evFork, 0);

    // Producer chain on sA: one colsum kernel + event per chunk
    for (int c = 0; c < NCHUNK; ++c) {
        colsum_chunk<<<32, 256, 0, sA>>>(w, c);
        cudaEventRecord(ev[c], sA);
    }

    // Consumer chain on the main stream: rowdot chunk c waits its event.
    // (Also joins sA back into the main stream by the last wait.)
    for (int c = 0; c < NCHUNK; ++c) {
        cudaStreamWaitEvent(0, ev[c], 0);
        rowdot_chunk<<<512, 256>>>(x, out, c, c == NCHUNK - 1);
    }
}

// round 6
// speedup vs baseline: 2.7761x; 2.7761x over previous
#include <cuda_runtime.h>

// Fixed shapes per reference: B=4096, IN=HID=8192, fp32
#define IN_DIM    8192
#define HID_DIM   8192
#define COL4      (IN_DIM / 4)          // 2048 float4 per W/x row
#define NCHUNK    4
#define CHUNK_F4  (COL4 / NCHUNK)       // 512 float4 = 2048 floats per chunk
#define ROW_GRPS  128                   // row groups in colsum partials
#define ROWS_PER_GRP (HID_DIM / ROW_GRPS)   // 64

// Device-global scratch (allocation-free rule: device globals allowed)
__device__ float g_partial[ROW_GRPS * IN_DIM];   // 4 MB
__device__ float g_wsum[IN_DIM];                 // 32 KB
__device__ float g_acc[4096];                    // per-row accumulator

// ---- colsum_chunk_partial: partial col sums for column-chunk c ----
// grid = (2, 128), block = 256. Same access pattern as the proven 80%-spec
// colsum: thread owns one float4 column, sums 64 consecutive rows.
__global__ __launch_bounds__(256) void colsum_chunk_partial(
        const float* __restrict__ w, int c) {
    const int col4 = c * CHUNK_F4 + blockIdx.x * 256 + threadIdx.x;
    const int r0   = blockIdx.y * ROWS_PER_GRP;
    const float4* __restrict__ w4 = reinterpret_cast<const float4*>(w);

    float4 acc = make_float4(0.f, 0.f, 0.f, 0.f);
    #pragma unroll 8
    for (int r = 0; r < ROWS_PER_GRP; ++r) {
        float4 v = __ldg(&w4[(size_t)(r0 + r) * COL4 + col4]);
        acc.x += v.x; acc.y += v.y; acc.z += v.z; acc.w += v.w;
    }
    reinterpret_cast<float4*>(g_partial)[(size_t)blockIdx.y * COL4 + col4] = acc;
}

// ---- reduce_chunk: collapse 128 partials -> g_wsum slice for chunk c ----
// grid = 2, block = 256 (one thread per float4 column of the chunk).
__global__ __launch_bounds__(256) void reduce_chunk(int c) {
    const int col4 = c * CHUNK_F4 + blockIdx.x * 256 + threadIdx.x;
    const float4* __restrict__ p4 = reinterpret_cast<const float4*>(g_partial);
    float4 acc = make_float4(0.f, 0.f, 0.f, 0.f);
    #pragma unroll 8
    for (int g = 0; g < ROW_GRPS; ++g) {
        float4 v = p4[(size_t)g * COL4 + col4];
        acc.x += v.x; acc.y += v.y; acc.z += v.z; acc.w += v.w;
    }
    reinterpret_cast<float4*>(g_wsum)[col4] = acc;
}

// ---- rowdot_chunk: g_acc[b] += dot(x[b, chunk c], wsum[chunk c]) ----
// grid = 512, block = 256. Block owns 8 rows; 2 k-steps of 256 f4 each ->
// 16 independent x LDG.128 per thread. Last chunk: *0.75 and write out.
__global__ __launch_bounds__(256) void rowdot_chunk(const float* __restrict__ x,
                                                    float* __restrict__ out,
                                                    int c, int is_last) {
    const int t     = threadIdx.x;
    const int lane  = t & 31;
    const int wid   = t >> 5;
    const int rbase = blockIdx.x * 8;

    const float4* __restrict__ x4 = reinterpret_cast<const float4*>(x);
    const float4* __restrict__ w4 = reinterpret_cast<const float4*>(g_wsum);

    float acc[8];
    #pragma unroll
    for (int r = 0; r < 8; ++r) acc[r] = 0.f;

    #pragma unroll
    for (int k = 0; k < CHUNK_F4 / 256; ++k) {       // 2 k-steps
        const int i = c * CHUNK_F4 + k * 256 + t;
        float4 wv = __ldg(&w4[i]);                   // L2-resident

        float4 xv[8];
        #pragma unroll
        for (int r = 0; r < 8; ++r)                  // 8 independent streams
            xv[r] = __ldg(&x4[(size_t)(rbase + r) * COL4 + i]);

        #pragma unroll
        for (int r = 0; r < 8; ++r) {
            acc[r] = fmaf(xv[r].x, wv.x, acc[r]);
            acc[r] = fmaf(xv[r].y, wv.y, acc[r]);
            acc[r] = fmaf(xv[r].z, wv.z, acc[r]);
            acc[r] = fmaf(xv[r].w, wv.w, acc[r]);
        }
    }

    #pragma unroll
    for (int r = 0; r < 8; ++r) {
        #pragma unroll
        for (int off = 16; off > 0; off >>= 1)
            acc[r] += __shfl_xor_sync(0xFFFFFFFFu, acc[r], off);
    }

    __shared__ float s[8][9];                        // [row][warp], padded
    if (lane == 0) {
        #pragma unroll
        for (int r = 0; r < 8; ++r) s[r][wid] = acc[r];
    }
    __syncthreads();

    // warp r finalizes row r
    float v = (lane < 8) ? s[wid][lane] : 0.f;
    #pragma unroll
    for (int off = 4; off > 0; off >>= 1)
        v += __shfl_xor_sync(0xFFFFFFFFu, v, off);

    if (lane == 0) {
        const int row = rbase + wid;
        float total = (c == 0) ? v : (g_acc[row] + v);   // c==0 overwrites stale
        if (is_last) out[row] = total * 0.75f;           // (/2) * 1.5
        else         g_acc[row] = total;
    }
}

extern "C" void kernel_launch(void* const* d_in, const int* in_sizes, int n_in,
                              void* d_out, int out_size) {
    const float* x = (const float*)d_in[0];   // [B, IN]
    const float* w = (const float*)d_in[1];   // [HID, IN]
    float* out = (float*)d_out;               // [B, 1]

    // One-time host-side objects (no device memory)
    static cudaStream_t sA = nullptr;
    static cudaEvent_t  evFork = nullptr;
    static cudaEvent_t  ev[NCHUNK];
    if (!sA) {
        cudaStreamCreateWithFlags(&sA, cudaStreamNonBlocking);
        cudaEventCreateWithFlags(&evFork, cudaEventDisableTiming);
        for (int c = 0; c < NCHUNK; ++c)
            cudaEventCreateWithFlags(&ev[c], cudaEventDisableTiming);
    }

    // Fork producer stream off the capture stream
    cudaEventRecord(evFork, 0);
    cudaStreamWaitEvent(sA, evFork, 0);

    // Producer chain: per chunk, partial colsum (256 blocks) + tiny reduce
    for (int c = 0; c < NCHUNK; ++c) {
        dim3 g(2, ROW_GRPS);
        colsum_chunk_partial<<<g, 256, 0, sA>>>(w, c);
        reduce_chunk<<<2, 256, 0, sA>>>(c);
        cudaEventRecord(ev[c], sA);
    }

    // Consumer chain on the main stream; last wait joins sA back.
    for (int c = 0; c < NCHUNK; ++c) {
        cudaStreamWaitEvent(0, ev[c], 0);
        rowdot_chunk<<<512, 256>>>(x, out, c, c == NCHUNK - 1);
    }
}

// round 7
// speedup vs baseline: 2.8122x; 1.0130x over previous
#include <cuda_runtime.h>

// Fixed shapes per reference: B=4096, IN=HID=8192, fp32
#define IN_DIM    8192
#define HID_DIM   8192
#define COL4      (IN_DIM / 4)          // 2048 float4 per W/x row
#define NCHUNK    4
#define CHUNK_F4  (COL4 / NCHUNK)       // 512 float4 per chunk
#define CS_XBLK   (CHUNK_F4 / 256)      // 2 column-groups per chunk
#define ROW_GRPS  128
#define ROWS_PER_GRP (HID_DIM / ROW_GRPS)   // 64

// Device-global scratch (allocation-free rule: device globals allowed)
__device__ float    g_partial[ROW_GRPS * IN_DIM];   // 4 MB
__device__ float    g_wsum[IN_DIM];                 // 32 KB
__device__ float    g_acc[4096];                    // per-row accumulator
__device__ unsigned g_ctr[NCHUNK * CS_XBLK];        // zero-init; wraps -> replay-safe

// ---- colsum_chunk_fused: col sums of W for column-chunk c, fused reduce ----
// grid = (2, 128), block = 256. Thread owns one float4 column, sums 64 rows
// (proven 80%-of-spec pattern). Last-arriving block of each column group
// reduces all 128 partials in fixed order and writes the wsum slice.
__global__ __launch_bounds__(256) void colsum_chunk_fused(
        const float* __restrict__ w, int c) {
    const int t    = threadIdx.x;
    const int col4 = c * CHUNK_F4 + blockIdx.x * 256 + t;
    const int r0   = blockIdx.y * ROWS_PER_GRP;
    const float4* __restrict__ w4 = reinterpret_cast<const float4*>(w);

    float4 acc = make_float4(0.f, 0.f, 0.f, 0.f);
    #pragma unroll 8
    for (int r = 0; r < ROWS_PER_GRP; ++r) {
        float4 v = __ldg(&w4[(size_t)(r0 + r) * COL4 + col4]);
        acc.x += v.x; acc.y += v.y; acc.z += v.z; acc.w += v.w;
    }
    reinterpret_cast<float4*>(g_partial)[(size_t)blockIdx.y * COL4 + col4] = acc;

    __threadfence();
    __syncthreads();

    __shared__ unsigned s_last;
    if (t == 0) {
        unsigned prev = atomicInc(&g_ctr[c * CS_XBLK + blockIdx.x],
                                  ROW_GRPS - 1);          // wraps to 0
        s_last = (prev == ROW_GRPS - 1);
    }
    __syncthreads();

    if (s_last) {
        __threadfence();   // acquire all blocks' partials
        const float4* __restrict__ p4 = reinterpret_cast<const float4*>(g_partial);
        float4 s = make_float4(0.f, 0.f, 0.f, 0.f);
        #pragma unroll 8
        for (int g = 0; g < ROW_GRPS; ++g) {              // fixed order
            float4 v = p4[(size_t)g * COL4 + col4];
            s.x += v.x; s.y += v.y; s.z += v.z; s.w += v.w;
        }
        reinterpret_cast<float4*>(g_wsum)[col4] = s;
    }
}

// ---- rowdot_chunk: g_acc[b] += dot(x[b, chunk c], wsum[chunk c]) ----
// grid = 512, block = 256. Block owns 8 rows; 2 k-steps -> 16 independent
// x LDG.128 per thread. Last chunk: *0.75 and write out.
__global__ __launch_bounds__(256) void rowdot_chunk(const float* __restrict__ x,
                                                    float* __restrict__ out,
                                                    int c, int is_last) {
    const int t     = threadIdx.x;
    const int lane  = t & 31;
    const int wid   = t >> 5;
    const int rbase = blockIdx.x * 8;

    const float4* __restrict__ x4 = reinterpret_cast<const float4*>(x);
    const float4* __restrict__ w4 = reinterpret_cast<const float4*>(g_wsum);

    float acc[8];
    #pragma unroll
    for (int r = 0; r < 8; ++r) acc[r] = 0.f;

    #pragma unroll
    for (int k = 0; k < CHUNK_F4 / 256; ++k) {       // 2 k-steps
        const int i = c * CHUNK_F4 + k * 256 + t;
        float4 wv = __ldg(&w4[i]);                   // L2-resident

        float4 xv[8];
        #pragma unroll
        for (int r = 0; r < 8; ++r)                  // 8 independent streams
            xv[r] = __ldg(&x4[(size_t)(rbase + r) * COL4 + i]);

        #pragma unroll
        for (int r = 0; r < 8; ++r) {
            acc[r] = fmaf(xv[r].x, wv.x, acc[r]);
            acc[r] = fmaf(xv[r].y, wv.y, acc[r]);
            acc[r] = fmaf(xv[r].z, wv.z, acc[r]);
            acc[r] = fmaf(xv[r].w, wv.w, acc[r]);
        }
    }

    #pragma unroll
    for (int r = 0; r < 8; ++r) {
        #pragma unroll
        for (int off = 16; off > 0; off >>= 1)
            acc[r] += __shfl_xor_sync(0xFFFFFFFFu, acc[r], off);
    }

    __shared__ float s[8][9];                        // [row][warp], padded
    if (lane == 0) {
        #pragma unroll
        for (int r = 0; r < 8; ++r) s[r][wid] = acc[r];
    }
    __syncthreads();

    // warp r finalizes row r
    float v = (lane < 8) ? s[wid][lane] : 0.f;
    #pragma unroll
    for (int off = 4; off > 0; off >>= 1)
        v += __shfl_xor_sync(0xFFFFFFFFu, v, off);

    if (lane == 0) {
        const int row = rbase + wid;
        float total = (c == 0) ? v : (g_acc[row] + v);   // c==0 overwrites stale
        if (is_last) out[row] = total * 0.75f;           // (/2) * 1.5
        else         g_acc[row] = total;
    }
}

extern "C" void kernel_launch(void* const* d_in, const int* in_sizes, int n_in,
                              void* d_out, int out_size) {
    const float* x = (const float*)d_in[0];   // [B, IN]
    const float* w = (const float*)d_in[1];   // [HID, IN]
    float* out = (float*)d_out;               // [B, 1]

    // One-time host-side objects (no device memory)
    static cudaStream_t sA = nullptr;
    static cudaEvent_t  evFork = nullptr;
    static cudaEvent_t  ev[NCHUNK];
    if (!sA) {
        cudaStreamCreateWithFlags(&sA, cudaStreamNonBlocking);
        cudaEventCreateWithFlags(&evFork, cudaEventDisableTiming);
        for (int c = 0; c < NCHUNK; ++c)
            cudaEventCreateWithFlags(&ev[c], cudaEventDisableTiming);
    }

    // Fork producer stream off the capture stream
    cudaEventRecord(evFork, 0);
    cudaStreamWaitEvent(sA, evFork, 0);

    // Producer chain: one fused colsum kernel per chunk (256 blocks each)
    for (int c = 0; c < NCHUNK; ++c) {
        dim3 g(CS_XBLK, ROW_GRPS);
        colsum_chunk_fused<<<g, 256, 0, sA>>>(w, c);
        cudaEventRecord(ev[c], sA);
    }

    // Consumer chain on the main stream; last wait joins sA back.
    for (int c = 0; c < NCHUNK; ++c) {
        cudaStreamWaitEvent(0, ev[c], 0);
        rowdot_chunk<<<512, 256>>>(x, out, c, c == NCHUNK - 1);
    }
}

// round 8
// speedup vs baseline: 4.4404x; 1.5790x over previous
#include <cuda_runtime.h>

// Fixed shapes per reference: B=4096, IN=HID=8192, fp32
#define IN_DIM   8192
#define HID_DIM  8192
#define COL4     (IN_DIM / 4)                    // 2048 float4 per row
#define ROW_GRPS 128                             // colsum row groups
#define ROWS_PER_GRP (HID_DIM / ROW_GRPS)        // 64 rows per block

// Device-global scratch (allocation-free rule: device globals allowed)
__device__ float g_partial[ROW_GRPS * IN_DIM];   // 4 MB
__device__ float g_wsum[IN_DIM];                 // 32 KB

// ---------------- Kernel 1: partial column sums of W [HID, IN] ----------------
// grid = (8, 128) = 1024 blocks, block = 256. Thread owns one float4 column,
// sums 64 consecutive rows (unroll 8 -> 8 outstanding LDG.128).
__global__ __launch_bounds__(256) void colsum_partial(const float* __restrict__ w) {
    const int col4 = blockIdx.x * 256 + threadIdx.x;        // 0..2047
    const int r0   = blockIdx.y * ROWS_PER_GRP;
    const float4* __restrict__ w4 = reinterpret_cast<const float4*>(w);

    float4 acc = make_float4(0.f, 0.f, 0.f, 0.f);
    #pragma unroll 8
    for (int r = 0; r < ROWS_PER_GRP; ++r) {
        float4 v = __ldg(&w4[(size_t)(r0 + r) * COL4 + col4]);
        acc.x += v.x; acc.y += v.y; acc.z += v.z; acc.w += v.w;
    }
    reinterpret_cast<float4*>(g_partial)[(size_t)blockIdx.y * COL4 + col4] = acc;
}

// ---------------- Kernel 2: reduce 128 partials -> g_wsum ----------------
// grid = 8, block = 256. L2-resident traffic (~4 MB), ~1.5 us.
__global__ __launch_bounds__(256) void reduce_partial() {
    const int col4 = blockIdx.x * 256 + threadIdx.x;
    const float4* __restrict__ p4 = reinterpret_cast<const float4*>(g_partial);
    float4 acc = make_float4(0.f, 0.f, 0.f, 0.f);
    #pragma unroll 8
    for (int g = 0; g < ROW_GRPS; ++g) {
        float4 v = p4[(size_t)g * COL4 + col4];
        acc.x += v.x; acc.y += v.y; acc.z += v.z; acc.w += v.w;
    }
    reinterpret_cast<float4*>(g_wsum)[col4] = acc;
}

// ---------------- Kernel 3: out[b] = 0.75 * dot(x[b], wsum), 2 rows/block ----
// grid = 2048, block = 256. Per thread: 8 k-steps x 2 independent row streams
// (8-deep MLP per row, 16 LDG.128 total), one block reduction for both rows.
__global__ __launch_bounds__(256) void rowdot2(const float* __restrict__ x,
                                               float* __restrict__ out, int B) {
    const int t     = threadIdx.x;
    const int lane  = t & 31;
    const int wid   = t >> 5;
    const int rbase = blockIdx.x * 2;

    const float4* __restrict__ x0 =
        reinterpret_cast<const float4*>(x + (size_t)rbase * IN_DIM);
    const float4* __restrict__ x1 =
        reinterpret_cast<const float4*>(x + (size_t)(rbase + 1) * IN_DIM);
    const float4* __restrict__ w4 = reinterpret_cast<const float4*>(g_wsum);

    float a0 = 0.f, a1 = 0.f;
    #pragma unroll
    for (int k = 0; k < COL4 / 256; ++k) {           // 8 k-steps
        const int i = t + k * 256;
        float4 wv  = __ldg(&w4[i]);                  // L2-resident
        float4 v0  = __ldg(&x0[i]);
        float4 v1  = __ldg(&x1[i]);
        a0 = fmaf(v0.x, wv.x, a0);
        a0 = fmaf(v0.y, wv.y, a0);
        a0 = fmaf(v0.z, wv.z, a0);
        a0 = fmaf(v0.w, wv.w, a0);
        a1 = fmaf(v1.x, wv.x, a1);
        a1 = fmaf(v1.y, wv.y, a1);
        a1 = fmaf(v1.z, wv.z, a1);
        a1 = fmaf(v1.w, wv.w, a1);
    }

    #pragma unroll
    for (int off = 16; off > 0; off >>= 1) {
        a0 += __shfl_xor_sync(0xFFFFFFFFu, a0, off);
        a1 += __shfl_xor_sync(0xFFFFFFFFu, a1, off);
    }

    __shared__ float s[2][9];                        // [row][warp], padded
    if (lane == 0) { s[0][wid] = a0; s[1][wid] = a1; }
    __syncthreads();

    // warp 0 -> row 0, warp 1 -> row 1
    if (wid < 2) {
        float v = (lane < 8) ? s[wid][lane] : 0.f;
        #pragma unroll
        for (int off = 4; off > 0; off >>= 1)
            v += __shfl_xor_sync(0xFFFFFFFFu, v, off);
        if (lane == 0 && rbase + wid < B)
            out[rbase + wid] = v * 0.75f;            // (/2) * 1.5
    }
}

extern "C" void kernel_launch(void* const* d_in, const int* in_sizes, int n_in,
                              void* d_out, int out_size) {
    const float* x = (const float*)d_in[0];   // [B, IN]
    const float* w = (const float*)d_in[1];   // [HID, IN]
    float* out = (float*)d_out;               // [B, 1]
    const int B = in_sizes[0] / IN_DIM;

    dim3 g1(COL4 / 256, ROW_GRPS);            // (8, 128) = 1024 blocks
    colsum_partial<<<g1, 256>>>(w);
    reduce_partial<<<COL4 / 256, 256>>>();
    rowdot2<<<(B + 1) / 2, 256>>>(x, out, B);
}

// round 9
// speedup vs baseline: 4.5020x; 1.0139x over previous
#include <cuda_runtime.h>

// Fixed shapes per reference: B=4096, IN=HID=8192, fp32
#define IN_DIM   8192
#define HID_DIM  8192
#define COL4     (IN_DIM / 4)                    // 2048 float4 per row
#define ROW_GRPS 128                             // colsum row groups
#define ROWS_PER_GRP (HID_DIM / ROW_GRPS)        // 64 rows per block
#define RD_GRID  1184                            // 148 SMs x 8 resident CTAs

// Device-global scratch (allocation-free rule: device globals allowed)
__device__ float g_partial[ROW_GRPS * IN_DIM];   // 4 MB
__device__ float g_wsum[IN_DIM];                 // 32 KB

// ---------------- Kernel 1: partial column sums of W [HID, IN] ----------------
// grid = (8, 128) = 1024 blocks, block = 256. At the 6.4 TB/s chip ceiling.
__global__ __launch_bounds__(256) void colsum_partial(const float* __restrict__ w) {
    const int col4 = blockIdx.x * 256 + threadIdx.x;        // 0..2047
    const int r0   = blockIdx.y * ROWS_PER_GRP;
    const float4* __restrict__ w4 = reinterpret_cast<const float4*>(w);

    float4 acc = make_float4(0.f, 0.f, 0.f, 0.f);
    #pragma unroll 8
    for (int r = 0; r < ROWS_PER_GRP; ++r) {
        float4 v = __ldg(&w4[(size_t)(r0 + r) * COL4 + col4]);
        acc.x += v.x; acc.y += v.y; acc.z += v.z; acc.w += v.w;
    }
    reinterpret_cast<float4*>(g_partial)[(size_t)blockIdx.y * COL4 + col4] = acc;
}

// ---------------- Kernel 2: reduce 128 partials -> g_wsum ----------------
__global__ __launch_bounds__(256) void reduce_partial() {
    const int col4 = blockIdx.x * 256 + threadIdx.x;
    const float4* __restrict__ p4 = reinterpret_cast<const float4*>(g_partial);
    float4 acc = make_float4(0.f, 0.f, 0.f, 0.f);
    #pragma unroll 8
    for (int g = 0; g < ROW_GRPS; ++g) {
        float4 v = p4[(size_t)g * COL4 + col4];
        acc.x += v.x; acc.y += v.y; acc.z += v.z; acc.w += v.w;
    }
    reinterpret_cast<float4*>(g_wsum)[col4] = acc;
}

// ---------------- Kernel 3: out[b] = 0.75 * dot(x[b], wsum) ----------------
// R1's proven block-per-row body, made grid-stride persistent at exactly one
// wave (1184 blocks). wsum via __ldg stays L1-resident across rows.
__global__ __launch_bounds__(256) void rowdot(const float* __restrict__ x,
                                              float* __restrict__ out, int B) {
    const int t    = threadIdx.x;
    const int lane = t & 31;
    const int wid  = t >> 5;
    const float4* __restrict__ w4 = reinterpret_cast<const float4*>(g_wsum);

    __shared__ float warp_sums[2][8];     // double-buffered block reduce

    int it = 0;
    for (int row = blockIdx.x; row < B; row += RD_GRID, ++it) {
        const float4* __restrict__ x4 =
            reinterpret_cast<const float4*>(x + (size_t)row * IN_DIM);

        float acc = 0.f;
        #pragma unroll
        for (int k = 0; k < COL4 / 256; ++k) {     // 8 LDG.128 on x, MLP=8
            const int i = t + k * 256;
            float4 xv = __ldg(&x4[i]);
            float4 wv = __ldg(&w4[i]);             // L1-resident
            acc = fmaf(xv.x, wv.x, acc);
            acc = fmaf(xv.y, wv.y, acc);
            acc = fmaf(xv.z, wv.z, acc);
            acc = fmaf(xv.w, wv.w, acc);
        }

        #pragma unroll
        for (int off = 16; off > 0; off >>= 1)
            acc += __shfl_xor_sync(0xFFFFFFFFu, acc, off);

        const int buf = it & 1;
        if (lane == 0) warp_sums[buf][wid] = acc;
        __syncthreads();

        if (wid == 0) {
            float v = (lane < 8) ? warp_sums[buf][lane] : 0.f;
            #pragma unroll
            for (int off = 4; off > 0; off >>= 1)
                v += __shfl_xor_sync(0xFFFFFFFFu, v, off);
            if (lane == 0) out[row] = v * 0.75f;   // (/2) * 1.5
        }
        // next iteration uses the other buffer; its __syncthreads orders reuse
    }
}

extern "C" void kernel_launch(void* const* d_in, const int* in_sizes, int n_in,
                              void* d_out, int out_size) {
    const float* x = (const float*)d_in[0];   // [B, IN]
    const float* w = (const float*)d_in[1];   // [HID, IN]
    float* out = (float*)d_out;               // [B, 1]
    const int B = in_sizes[0] / IN_DIM;

    dim3 g1(COL4 / 256, ROW_GRPS);            // (8, 128)
    colsum_partial<<<g1, 256>>>(w);
    reduce_partial<<<COL4 / 256, 256>>>();
    rowdot<<<RD_GRID, 256>>>(x, out, B);
}